// round 7
// baseline (speedup 1.0000x reference)
#include <cuda_runtime.h>

// QCONVbk closed form:
//   out[b,f,h,w] = sum_c prod_{k=1..8} cos( patch_k(b,c,h,w) + weights[0,k] )
// (CNOT ring maps Z0 -> Z1..Z8 in the Heisenberg picture; RX product state
//  gives <Zq> = cos(a_q + w_q); wire-0 angle drops out.)
//
// Parallelization: one thread per (pixel, channel) = 32768 threads.
// 4 consecutive lanes share a pixel (c = tid & 3); channel sum via 2x shfl_xor.
// Each lane then writes filter copies f=c and f=c+4 (8 filters total per pixel).

#define BB 8
#define CC 4
#define HH 32
#define WW 32
#define FF 8

__global__ void __launch_bounds__(256) qconv_kernel(
    const float* __restrict__ x,      // (B, C, H, W)
    const float* __restrict__ wts,    // (1, 9)
    float* __restrict__ out)          // (B, 8, H, W)
{
    int tid = blockIdx.x * blockDim.x + threadIdx.x;   // 0 .. 32767
    int c   = tid & 3;
    int pix = tid >> 2;                                // 0 .. 8191
    int w = pix & (WW - 1);
    int h = (pix >> 5) & (HH - 1);
    int b = pix >> 10;

    // weights (wire 0 irrelevant): wk1..wk8 = wts[1..8], vectorized loads
    const float4 wa = *(const float4*)(wts);       // wts[0..3]
    const float4 wb = *(const float4*)(wts + 4);   // wts[4..7]
    const float  wk8 = __ldg(&wts[8]);

    bool hu = (h > 0), hd = (h < HH - 1);
    bool wl = (w > 0), wr = (w < WW - 1);

    const float* xc = x + (((b * CC + c) << 10) + (h << 5) + w);

    // taps k=1..8 (k=0 at (-1,-1) drops out); zero pad -> angle 0
    float a1 = hu        ? __ldg(xc - WW    ) : 0.0f;   // (-1, 0)
    float a2 = (hu && wr)? __ldg(xc - WW + 1) : 0.0f;   // (-1,+1)
    float a3 = wl        ? __ldg(xc - 1     ) : 0.0f;   // ( 0,-1)
    float a4 =             __ldg(xc         );          // ( 0, 0)
    float a5 = wr        ? __ldg(xc + 1     ) : 0.0f;   // ( 0,+1)
    float a6 = (hd && wl)? __ldg(xc + WW - 1) : 0.0f;   // (+1,-1)
    float a7 = hd        ? __ldg(xc + WW    ) : 0.0f;   // (+1, 0)
    float a8 = (hd && wr)? __ldg(xc + WW + 1) : 0.0f;   // (+1,+1)

    float c1 = __cosf(a1 + wa.y);
    float c2 = __cosf(a2 + wa.z);
    float c3 = __cosf(a3 + wa.w);
    float c4 = __cosf(a4 + wb.x);
    float c5 = __cosf(a5 + wb.y);
    float c6 = __cosf(a6 + wb.z);
    float c7 = __cosf(a7 + wb.w);
    float c8 = __cosf(a8 + wk8);

    // pairwise product tree (depth 3)
    float p = ((c1 * c2) * (c3 * c4)) * ((c5 * c6) * (c7 * c8));

    // sum over the 4 channels held by 4 adjacent lanes
    p += __shfl_xor_sync(0xFFFFFFFFu, p, 1);
    p += __shfl_xor_sync(0xFFFFFFFFu, p, 2);

    // each lane writes 2 of the 8 identical filter copies
    float* ob = out + ((b << 13) + (h << 5) + w);
    ob[(size_t)(c    ) << 10] = p;
    ob[(size_t)(c + 4) << 10] = p;
}

extern "C" void kernel_launch(void* const* d_in, const int* in_sizes, int n_in,
                              void* d_out, int out_size) {
    const float* x   = (const float*)d_in[0];   // (8,4,32,32)
    const float* wts = (const float*)d_in[1];   // (1,9)
    float* out = (float*)d_out;                 // (8,8,32,32)
    (void)in_sizes; (void)n_in; (void)out_size;

    const int total_threads = BB * HH * WW * CC;   // 32768
    qconv_kernel<<<total_threads / 256, 256>>>(x, wts, out);
}

// round 10
// speedup vs baseline: 1.5105x; 1.5105x over previous
#include <cuda_runtime.h>

// QCONVbk closed form:
//   out[b,f,h,w] = sum_c prod_{k=1..8} cos( patch_k(b,c,h,w) + weights[0,k] )
// (CNOT ring maps Z0 -> Z1..Z8 in the Heisenberg picture; RX product state
//  gives <Zq> = cos(a_q + w_q); the wire-0 angle drops out of <Z0>.)
//
// One thread per (pixel, channel) = 32768 threads; 4 consecutive lanes share a
// pixel, channel sum via 2x shfl_xor; each lane writes 2 of 8 filter copies.
// Warp-uniform interior fast path: fully in-bounds warps issue 8 unpredicated
// LDGs back-to-back (no boundary ISETPs on the critical path).

#define BB 8
#define CC 4
#define HH 32
#define WW 32
#define FF 8

__global__ void __launch_bounds__(256) qconv_kernel(
    const float* __restrict__ x,      // (B, C, H, W)
    const float* __restrict__ wts,    // (1, 9)
    float* __restrict__ out)          // (B, 8, H, W)
{
    int tid = blockIdx.x * blockDim.x + threadIdx.x;   // 0 .. 32767
    int c   = tid & 3;
    int pix = tid >> 2;                                // 0 .. 8191
    int w = pix & (WW - 1);
    int h = (pix >> 5) & (HH - 1);
    int b = pix >> 10;

    const float* xc = x + (((b * CC + c) << 10) + (h << 5) + w);

    bool interior = (h > 0) & (h < HH - 1) & (w > 0) & (w < WW - 1);

    float a1, a2, a3, a4, a5, a6, a7, a8;
    if (__all_sync(0xFFFFFFFFu, interior)) {
        // fast path: 8 unpredicated loads, issued back-to-back
        a1 = __ldg(xc - WW    );
        a2 = __ldg(xc - WW + 1);
        a3 = __ldg(xc - 1     );
        a4 = __ldg(xc         );
        a5 = __ldg(xc + 1     );
        a6 = __ldg(xc + WW - 1);
        a7 = __ldg(xc + WW    );
        a8 = __ldg(xc + WW + 1);
    } else {
        bool hu = (h > 0), hd = (h < HH - 1);
        bool wl = (w > 0), wr = (w < WW - 1);
        a1 = hu        ? __ldg(xc - WW    ) : 0.0f;   // (-1, 0)
        a2 = (hu && wr)? __ldg(xc - WW + 1) : 0.0f;   // (-1,+1)
        a3 = wl        ? __ldg(xc - 1     ) : 0.0f;   // ( 0,-1)
        a4 =             __ldg(xc         );          // ( 0, 0)
        a5 = wr        ? __ldg(xc + 1     ) : 0.0f;   // ( 0,+1)
        a6 = (hd && wl)? __ldg(xc + WW - 1) : 0.0f;   // (+1,-1)
        a7 = hd        ? __ldg(xc + WW    ) : 0.0f;   // (+1, 0)
        a8 = (hd && wr)? __ldg(xc + WW + 1) : 0.0f;   // (+1,+1)
    }

    // weights 1..8 (wire 0 irrelevant); two vector loads + one scalar
    const float4 wa  = __ldg((const float4*)(wts));       // wts[0..3]
    const float4 wb  = __ldg((const float4*)(wts + 4));   // wts[4..7]
    const float  wk8 = __ldg(&wts[8]);

    float c1 = __cosf(a1 + wa.y);
    float c2 = __cosf(a2 + wa.z);
    float c3 = __cosf(a3 + wa.w);
    float c4 = __cosf(a4 + wb.x);
    float c5 = __cosf(a5 + wb.y);
    float c6 = __cosf(a6 + wb.z);
    float c7 = __cosf(a7 + wb.w);
    float c8 = __cosf(a8 + wk8);

    // pairwise product tree (depth 3)
    float p = ((c1 * c2) * (c3 * c4)) * ((c5 * c6) * (c7 * c8));

    // sum over the 4 channels held by 4 adjacent lanes
    p += __shfl_xor_sync(0xFFFFFFFFu, p, 1);
    p += __shfl_xor_sync(0xFFFFFFFFu, p, 2);

    // each lane writes 2 of the 8 identical filter copies
    float* ob = out + ((b << 13) + (h << 5) + w);
    ob[(size_t)(c    ) << 10] = p;
    ob[(size_t)(c + 4) << 10] = p;
}

extern "C" void kernel_launch(void* const* d_in, const int* in_sizes, int n_in,
                              void* d_out, int out_size) {
    const float* x   = (const float*)d_in[0];   // (8,4,32,32)
    const float* wts = (const float*)d_in[1];   // (1,9)
    float* out = (float*)d_out;                 // (8,8,32,32)
    (void)in_sizes; (void)n_in; (void)out_size;

    const int total_threads = BB * HH * WW * CC;   // 32768
    qconv_kernel<<<total_threads / 256, 256>>>(x, wts, out);
}